// round 4
// baseline (speedup 1.0000x reference)
#include <cuda_runtime.h>
#include <math.h>

// B=8, C=128, N=8192, K=9, PAD=4, DIL=1, STR=1, L=N
#define Bv 8
#define Cv 128
#define Nv 8192
#define Kv 9
#define HALF_K 4
#define TL 128           // l positions per block tile
#define THREADS 256
#define CPB 32           // channels per block
#define NITER 4          // CPB / 8 warps

__global__ __launch_bounds__(THREADS)
void swconv_kernel(const float* __restrict__ x,
                   const float* __restrict__ coords,
                   const float* __restrict__ sigma,
                   const float* __restrict__ weight,
                   float* __restrict__ out)
{
    __shared__ float dwT[Kv][TL];     // [k][l] transposed for aligned float4 reads
    __shared__ float ws[CPB * Kv];

    const int b     = blockIdx.y;
    const int l0g   = blockIdx.x * TL;
    const int cbase = blockIdx.z * CPB;
    const int tid   = threadIdx.x;

    // ---- weights slice ----
    for (int i = tid; i < CPB * Kv; i += THREADS)
        ws[i] = weight[cbase * Kv + i];

    // ---- phase 1: dw[l][k], split across all 256 threads (k halves) ----
    {
        const int l_loc = tid & (TL - 1);
        const int khalf = tid >> 7;           // 0 -> k 0..4, 1 -> k 5..8
        const int l     = l0g + l_loc;
        const float* cb = coords + b * 3 * Nv;
        const float cx = cb[l];
        const float cy = cb[Nv + l];
        const float cz = cb[2 * Nv + l];
        const float inv_sig = 1.0f / sigma[0];
        const int k0 = khalf ? 5 : 0;
        const int k1 = khalf ? Kv : 5;
        for (int k = k0; k < k1; k++) {
            const int idx = l + k - HALF_K;
            float dx, dy, dz;
            if (idx >= 0 && idx < Nv) {
                dx = cb[idx]          - cx;
                dy = cb[Nv + idx]     - cy;
                dz = cb[2 * Nv + idx] - cz;
            } else {
                dx = -cx; dy = -cy; dz = -cz;   // zero-padded coords
            }
            const float sq   = dx * dx + dy * dy + dz * dz;
            const float dist = (sq > 0.0f) ? sqrtf(sq) : 0.0f;
            dwT[k][l_loc] = fmaxf(1.0f - dist * inv_sig, 0.0f);
        }
    }
    __syncthreads();

    const int lane = tid & 31;
    const int w_id = tid >> 5;          // warp -> channel offset within pass
    const int lq   = lane * 4;          // local l of first output
    const int lg   = l0g + lq;          // global l

    // distance weights for this thread's 4 outputs, register-cached, reused
    // across all NITER channel iterations
    float4 dq[Kv];
    #pragma unroll
    for (int k = 0; k < Kv; k++)
        dq[k] = *reinterpret_cast<const float4*>(&dwT[k][lq]);

    const bool interior = (l0g >= HALF_K) && (l0g + TL + HALF_K <= Nv);

    if (interior) {
        const int row0 = (b * Cv + cbase + w_id) * Nv;   // iter stride = 8*Nv
        const float* xb0 = x + row0;
        float*       ob0 = out + row0 + lg;

        // preload iter 0
        float4 m = *reinterpret_cast<const float4*>(xb0 + lg);
        float4 e = make_float4(0.f, 0.f, 0.f, 0.f);
        if (lane == 0)  e = *reinterpret_cast<const float4*>(xb0 + lg - 4);
        if (lane == 31) e = *reinterpret_cast<const float4*>(xb0 + lg + 4);

        #pragma unroll
        for (int it = 0; it < NITER; ++it) {
            // prefetch next channel's window before touching current data
            float4 mn = make_float4(0.f, 0.f, 0.f, 0.f);
            float4 en = make_float4(0.f, 0.f, 0.f, 0.f);
            if (it < NITER - 1) {
                const float* xn = xb0 + (it + 1) * 8 * Nv;
                mn = *reinterpret_cast<const float4*>(xn + lg);
                if (lane == 0)  en = *reinterpret_cast<const float4*>(xn + lg - 4);
                if (lane == 31) en = *reinterpret_cast<const float4*>(xn + lg + 4);
            }

            // neighbor exchange: left quad from lane-1, right quad from lane+1
            float xv[12];
            xv[4] = m.x; xv[5] = m.y; xv[6] = m.z; xv[7] = m.w;
            xv[0] = __shfl_up_sync(0xFFFFFFFFu, m.x, 1);
            xv[1] = __shfl_up_sync(0xFFFFFFFFu, m.y, 1);
            xv[2] = __shfl_up_sync(0xFFFFFFFFu, m.z, 1);
            xv[3] = __shfl_up_sync(0xFFFFFFFFu, m.w, 1);
            xv[8]  = __shfl_down_sync(0xFFFFFFFFu, m.x, 1);
            xv[9]  = __shfl_down_sync(0xFFFFFFFFu, m.y, 1);
            xv[10] = __shfl_down_sync(0xFFFFFFFFu, m.z, 1);
            xv[11] = __shfl_down_sync(0xFFFFFFFFu, m.w, 1);
            if (lane == 0)  { xv[0] = e.x; xv[1] = e.y; xv[2]  = e.z; xv[3]  = e.w; }
            if (lane == 31) { xv[8] = e.x; xv[9] = e.y; xv[10] = e.z; xv[11] = e.w; }

            const float* wc = &ws[(it * 8 + w_id) * Kv];
            float4 acc = make_float4(0.f, 0.f, 0.f, 0.f);
            #pragma unroll
            for (int k = 0; k < Kv; k++) {
                const float wk = wc[k];
                acc.x = fmaf(xv[k + 0] * dq[k].x, wk, acc.x);
                acc.y = fmaf(xv[k + 1] * dq[k].y, wk, acc.y);
                acc.z = fmaf(xv[k + 2] * dq[k].z, wk, acc.z);
                acc.w = fmaf(xv[k + 3] * dq[k].w, wk, acc.w);
            }
            *reinterpret_cast<float4*>(ob0 + it * 8 * Nv) = acc;

            m = mn; e = en;
        }
    } else {
        // boundary tiles (2 of 64): simple guarded path
        #pragma unroll
        for (int it = 0; it < NITER; ++it) {
            const int c = cbase + it * 8 + w_id;
            const float* xb = x + (b * Cv + c) * Nv;
            float xv[12];
            #pragma unroll
            for (int j = 0; j < 12; j++) {
                const int idx = lg - HALF_K + j;
                xv[j] = (idx >= 0 && idx < Nv) ? xb[idx] : 0.0f;
            }
            const float* wc = &ws[(it * 8 + w_id) * Kv];
            float4 acc = make_float4(0.f, 0.f, 0.f, 0.f);
            #pragma unroll
            for (int k = 0; k < Kv; k++) {
                const float wk = wc[k];
                acc.x = fmaf(xv[k + 0] * dq[k].x, wk, acc.x);
                acc.y = fmaf(xv[k + 1] * dq[k].y, wk, acc.y);
                acc.z = fmaf(xv[k + 2] * dq[k].z, wk, acc.z);
                acc.w = fmaf(xv[k + 3] * dq[k].w, wk, acc.w);
            }
            *reinterpret_cast<float4*>(out + (b * Cv + c) * Nv + lg) = acc;
        }
    }
}

extern "C" void kernel_launch(void* const* d_in, const int* in_sizes, int n_in,
                              void* d_out, int out_size)
{
    const float* x      = (const float*)d_in[0];
    const float* coords = (const float*)d_in[1];
    const float* sigma  = (const float*)d_in[2];
    const float* weight = (const float*)d_in[3];
    float* out = (float*)d_out;

    dim3 grid(Nv / TL, Bv, Cv / CPB);   // (64, 8, 4)
    swconv_kernel<<<grid, THREADS>>>(x, coords, sigma, weight, out);
}